// round 4
// baseline (speedup 1.0000x reference)
#include <cuda_runtime.h>
#include <cuda_bf16.h>

#define NROWS 131072
#define GCOLS 512
#define FDIM  256
#define HDIM  128
#define KDIM  64
#define NDOM  8

#define K1PAD 272          // GEMM1 K padded: 259 -> 272 (17 k16 steps)
#define XS_STRIDE 280      // bf16 row stride for x tile and W1^T (140 b32; 140%32=12 -> conflict-free frags)
#define HS_STRIDE 136      // bf16 row stride for h tile and W2^T (68 b32; 68%32=4 -> conflict-free frags)

// ---------------- device scratch (no allocations allowed) ----------------
__device__ __align__(16) __nv_bfloat16 g_w1t[HDIM * XS_STRIDE];   // [n][k] = W1[k][n], bf16, zero-padded
__device__ __align__(16) __nv_bfloat16 g_w2t[KDIM * HS_STRIDE];   // [n][k] = W2[k][n], bf16, zero-padded
__device__ __align__(16) float g_dz[(size_t)NROWS * KDIM];        // 32 MB dz scratch

// ---------------- smem layout (bytes) ----------------
#define SM_XS   0
#define SM_W1   71680      // 128*280*2
#define SM_HS   143360     // + 71680
#define SM_W2   178176     // + 128*136*2 = 34816
#define SM_B1   195584     // + 64*136*2 = 17408
#define SM_B2   196096
#define SM_DOM  196352
#define SM_ALP  196864
#define SMEM_BYTES 196896

// m16n8k16 row.col bf16 -> f32 accumulate
__device__ __forceinline__ void mma_bf16(float (&c)[4], const unsigned (&a)[4],
                                         unsigned b0, unsigned b1) {
    asm volatile(
        "mma.sync.aligned.m16n8k16.row.col.f32.bf16.bf16.f32 "
        "{%0,%1,%2,%3}, {%4,%5,%6,%7}, {%8,%9}, {%0,%1,%2,%3};\n"
        : "+f"(c[0]), "+f"(c[1]), "+f"(c[2]), "+f"(c[3])
        : "r"(a[0]), "r"(a[1]), "r"(a[2]), "r"(a[3]), "r"(b0), "r"(b1));
}

// ---------------- prep: transpose + bf16-convert weights ----------------
__global__ void prep_kernel(const float* __restrict__ W1, const float* __restrict__ W2) {
    int i = blockIdx.x * blockDim.x + threadIdx.x;
    const int tot1 = HDIM * XS_STRIDE;
    if (i < tot1) {
        int n = i / XS_STRIDE, k = i - n * XS_STRIDE;
        float v = (k < FDIM + 3) ? W1[k * HDIM + n] : 0.f;
        g_w1t[i] = __float2bfloat16(v);
    } else {
        int j = i - tot1;
        if (j < KDIM * HS_STRIDE) {
            int n = j / HS_STRIDE, k = j - n * HS_STRIDE;
            float v = (k < HDIM) ? W2[k * KDIM + n] : 0.f;
            g_w2t[j] = __float2bfloat16(v);
        }
    }
}

// ---------------- main: conf + GEMM1 + GEMM2 -> dz ----------------
__global__ void __launch_bounds__(256, 1)
main_kernel(const float* __restrict__ z, const float* __restrict__ feats,
            const float* __restrict__ b1, const float* __restrict__ b2,
            const float* __restrict__ alphas, const int* __restrict__ dom) {
    extern __shared__ __align__(16) char smem[];
    __nv_bfloat16* xs  = (__nv_bfloat16*)(smem + SM_XS);
    __nv_bfloat16* w1s = (__nv_bfloat16*)(smem + SM_W1);
    __nv_bfloat16* hs  = (__nv_bfloat16*)(smem + SM_HS);
    __nv_bfloat16* w2s = (__nv_bfloat16*)(smem + SM_W2);
    float* b1s = (float*)(smem + SM_B1);
    float* b2s = (float*)(smem + SM_B2);
    int*   dms = (int*)(smem + SM_DOM);
    float* alp = (float*)(smem + SM_ALP);

    const int tid  = threadIdx.x;
    const int row0 = blockIdx.x * 128;

    // stage weights into smem (vectorized, from L2-hot device scratch)
    {
        const uint4* s1 = (const uint4*)g_w1t; uint4* d1 = (uint4*)w1s;
        for (int i = tid; i < (HDIM * XS_STRIDE * 2) / 16; i += 256) d1[i] = s1[i];
        const uint4* s2 = (const uint4*)g_w2t; uint4* d2 = (uint4*)w2s;
        for (int i = tid; i < (KDIM * HS_STRIDE * 2) / 16; i += 256) d2[i] = s2[i];
    }
    if (tid < HDIM) b1s[tid] = b1[tid];
    if (tid < KDIM) b2s[tid] = b2[tid];
    if (tid < NDOM) alp[tid] = alphas[tid];

    // feats -> xs (bf16), coalesced float4 reads
    {
        const float4* f4 = (const float4*)feats + (size_t)row0 * (FDIM / 4);
        for (int i = tid; i < 128 * (FDIM / 4); i += 256) {
            int r = i >> 6, c4 = i & 63;
            float4 v = f4[(size_t)r * (FDIM / 4) + c4];
            __nv_bfloat162 p0 = __floats2bfloat162_rn(v.x, v.y);
            __nv_bfloat162 p1 = __floats2bfloat162_rn(v.z, v.w);
            *(__nv_bfloat162*)(xs + r * XS_STRIDE + c4 * 4)     = p0;
            *(__nv_bfloat162*)(xs + r * XS_STRIDE + c4 * 4 + 2) = p1;
        }
    }

    // conf stats: one thread per row (closed-form softmax stats)
    if (tid < 128) {
        int rg = row0 + tid;
        int d  = dom[rg];
        dms[tid] = d;
        const float4* zr = (const float4*)(z + (size_t)rg * GCOLS + d * KDIM);
        float v[64];
        #pragma unroll
        for (int i = 0; i < 16; i++) {
            float4 t = zr[i];
            v[4*i] = t.x; v[4*i+1] = t.y; v[4*i+2] = t.z; v[4*i+3] = t.w;
        }
        float m1 = -3.4e38f, m2 = -3.4e38f;
        #pragma unroll
        for (int i = 0; i < 64; i++) {
            float x = v[i];
            if (x > m1) { m2 = m1; m1 = x; }
            else if (x > m2) { m2 = x; }
        }
        float S = 0.f, T = 0.f;
        #pragma unroll
        for (int i = 0; i < 64; i++) {
            float e = __expf(v[i] - m1);
            S += e;
            T += (v[i] - m1) * e;
        }
        float pmax = 1.f / S;
        float ent  = __logf(S) - T * pmax;
        float marg = (1.f - __expf(m2 - m1)) * pmax;
        __nv_bfloat16* xr = xs + tid * XS_STRIDE;
        xr[256] = __float2bfloat16(pmax);
        xr[257] = __float2bfloat16(ent);
        xr[258] = __float2bfloat16(marg);
        #pragma unroll
        for (int k = 259; k < K1PAD; k++) xr[k] = __float2bfloat16(0.f);
    }
    __syncthreads();

    const int lane = tid & 31, wid = tid >> 5;
    const int g = lane >> 2, t = lane & 3;

    // ---------- GEMM1: [128 x 272] @ [272 x 128] -> h ----------
    // warp grid 4(m) x 2(n): warp tile 32m x 64n
    {
        const int wm = wid & 3, wn = wid >> 2;
        float c1[2][8][4];
        #pragma unroll
        for (int mi = 0; mi < 2; mi++)
            #pragma unroll
            for (int nf = 0; nf < 8; nf++)
                #pragma unroll
                for (int q = 0; q < 4; q++) c1[mi][nf][q] = 0.f;

        const unsigned* xs32  = (const unsigned*)xs;
        const unsigned* w1s32 = (const unsigned*)w1s;

        #pragma unroll 4
        for (int ks = 0; ks < 17; ks++) {
            const int kp = ks * 8 + t;   // b32 pair index along k
            unsigned a[2][4];
            #pragma unroll
            for (int mi = 0; mi < 2; mi++) {
                int r = wm * 32 + mi * 16 + g;
                a[mi][0] = xs32[r * 140 + kp];
                a[mi][1] = xs32[(r + 8) * 140 + kp];
                a[mi][2] = xs32[r * 140 + kp + 4];
                a[mi][3] = xs32[(r + 8) * 140 + kp + 4];
            }
            #pragma unroll
            for (int nf = 0; nf < 8; nf++) {
                int n = wn * 64 + nf * 8 + g;
                unsigned b0 = w1s32[n * 140 + kp];
                unsigned bb = w1s32[n * 140 + kp + 4];
                mma_bf16(c1[0][nf], a[0], b0, bb);
                mma_bf16(c1[1][nf], a[1], b0, bb);
            }
        }

        // bias + relu -> hs (bf16, packed pairs)
        unsigned* hs32 = (unsigned*)hs;
        #pragma unroll
        for (int mi = 0; mi < 2; mi++) {
            int r = wm * 32 + mi * 16 + g;
            #pragma unroll
            for (int nf = 0; nf < 8; nf++) {
                int ncol = wn * 64 + nf * 8 + 2 * t;
                float bb0 = b1s[ncol], bb1 = b1s[ncol + 1];
                float h0 = fmaxf(c1[mi][nf][0] + bb0, 0.f);
                float h1 = fmaxf(c1[mi][nf][1] + bb1, 0.f);
                float h2 = fmaxf(c1[mi][nf][2] + bb0, 0.f);
                float h3 = fmaxf(c1[mi][nf][3] + bb1, 0.f);
                __nv_bfloat162 p0 = __floats2bfloat162_rn(h0, h1);
                __nv_bfloat162 p1 = __floats2bfloat162_rn(h2, h3);
                hs32[r * 68 + wn * 32 + nf * 4 + t]       = *(unsigned*)&p0;
                hs32[(r + 8) * 68 + wn * 32 + nf * 4 + t] = *(unsigned*)&p1;
            }
        }
    }
    __syncthreads();

    // ---------- GEMM2: [128 x 128] @ [128 x 64] -> dz ----------
    // warp grid 4(m) x 2(n): warp tile 32m x 32n
    {
        const int wm = wid & 3, wn = wid >> 2;
        float c2[2][4][4];
        #pragma unroll
        for (int mi = 0; mi < 2; mi++)
            #pragma unroll
            for (int nf = 0; nf < 4; nf++)
                #pragma unroll
                for (int q = 0; q < 4; q++) c2[mi][nf][q] = 0.f;

        const unsigned* hs32  = (const unsigned*)hs;
        const unsigned* w2s32 = (const unsigned*)w2s;

        #pragma unroll
        for (int ks = 0; ks < 8; ks++) {
            const int kp = ks * 8 + t;
            unsigned a[2][4];
            #pragma unroll
            for (int mi = 0; mi < 2; mi++) {
                int r = wm * 32 + mi * 16 + g;
                a[mi][0] = hs32[r * 68 + kp];
                a[mi][1] = hs32[(r + 8) * 68 + kp];
                a[mi][2] = hs32[r * 68 + kp + 4];
                a[mi][3] = hs32[(r + 8) * 68 + kp + 4];
            }
            #pragma unroll
            for (int nf = 0; nf < 4; nf++) {
                int n = wn * 32 + nf * 8 + g;
                unsigned b0 = w2s32[n * 68 + kp];
                unsigned bb = w2s32[n * 68 + kp + 4];
                mma_bf16(c2[0][nf], a[0], b0, bb);
                mma_bf16(c2[1][nf], a[1], b0, bb);
            }
        }

        // epilogue: + b2, * alpha(domain), write dz scratch
        #pragma unroll
        for (int mi = 0; mi < 2; mi++) {
            int rl = wm * 32 + mi * 16 + g;
            float al0 = alp[dms[rl]];
            float al1 = alp[dms[rl + 8]];
            #pragma unroll
            for (int nf = 0; nf < 4; nf++) {
                int col = wn * 32 + nf * 8 + 2 * t;
                float bb0 = b2s[col], bb1 = b2s[col + 1];
                float2 o0 = make_float2((c2[mi][nf][0] + bb0) * al0,
                                        (c2[mi][nf][1] + bb1) * al0);
                float2 o1 = make_float2((c2[mi][nf][2] + bb0) * al1,
                                        (c2[mi][nf][3] + bb1) * al1);
                *(float2*)&g_dz[(size_t)(row0 + rl) * KDIM + col]     = o0;
                *(float2*)&g_dz[(size_t)(row0 + rl + 8) * KDIM + col] = o1;
            }
        }
    }
}

// ---------------- scatter: out = z (+ dz on owned slice) ----------------
__global__ void __launch_bounds__(256)
scatter_kernel(const float* __restrict__ z, const int* __restrict__ dom,
               float* __restrict__ out) {
    int idx = blockIdx.x * 256 + threadIdx.x;      // over N*128 float4s
    int row = idx >> 7;
    int q   = idx & 127;
    float4 v = ((const float4*)z)[idx];
    int d = __ldg(dom + row);
    int qd = q - (d << 4);
    if ((unsigned)qd < 16u) {
        float4 dz = ((const float4*)g_dz)[row * 16 + qd];
        v.x += dz.x; v.y += dz.y; v.z += dz.z; v.w += dz.w;
    }
    ((float4*)out)[idx] = v;
}

extern "C" void kernel_launch(void* const* d_in, const int* in_sizes, int n_in,
                              void* d_out, int out_size) {
    const float* z      = (const float*)d_in[0];
    const float* feats  = (const float*)d_in[1];
    const float* W1     = (const float*)d_in[2];
    const float* b1     = (const float*)d_in[3];
    const float* W2     = (const float*)d_in[4];
    const float* b2     = (const float*)d_in[5];
    const float* alphas = (const float*)d_in[6];
    const int*   dom    = (const int*)d_in[7];
    float* out = (float*)d_out;

    cudaFuncSetAttribute(main_kernel, cudaFuncAttributeMaxDynamicSharedMemorySize,
                         SMEM_BYTES);

    const int preptot = HDIM * XS_STRIDE + KDIM * HS_STRIDE;
    prep_kernel<<<(preptot + 255) / 256, 256>>>(W1, W2);
    main_kernel<<<NROWS / 128, 256, SMEM_BYTES>>>(z, feats, b1, b2, alphas, dom);
    scatter_kernel<<<(NROWS * 128) / 256, 256>>>(z, dom, out);
}

// round 6
// speedup vs baseline: 1.0201x; 1.0201x over previous
#include <cuda_runtime.h>
#include <cuda_bf16.h>

#define NROWS 131072
#define GCOLS 512
#define FDIM  256
#define HDIM  128
#define KDIM  64
#define NDOM  8

#define K1PAD 272          // GEMM1 K padded: 259 -> 272 (17 k16 steps)
#define XS_STRIDE 280      // bf16 stride for x / W1^T (140 b32, conflict-free frag loads)
#define HS_STRIDE 136      // bf16 stride for h / W2^T (68 b32)
#define ZS_STRIDE 68       // f32 stride for owned z slice (17 float4 per row)

// ---------------- device scratch (no allocations allowed) ----------------
__device__ __align__(16) __nv_bfloat16 g_w1t[HDIM * XS_STRIDE];   // [n][k] = W1[k][n]
__device__ __align__(16) __nv_bfloat16 g_w2t[KDIM * HS_STRIDE];   // [n][k] = W2[k][n]

// ---------------- smem layout (bytes) ----------------
#define SM_XS   0                          // 128*280*2 = 71680
#define SM_W1   71680                      // 71680
#define SM_HS   143360                     // 128*136*2 = 34816
#define SM_W2   178176                     // 64*136*2  = 17408
#define SM_ZS   195584                     // 128*68*4  = 34816
#define SM_B1   230400                     // 512
#define SM_B2   230912                     // 256
#define SM_DOM  231168                     // 512
#define SM_ALP  231680                     // 32
#define SMEM_BYTES 231712

// m16n8k16 row.col bf16 -> f32 accumulate
__device__ __forceinline__ void mma_bf16(float (&c)[4], const unsigned (&a)[4],
                                         unsigned b0, unsigned b1) {
    asm volatile(
        "mma.sync.aligned.m16n8k16.row.col.f32.bf16.bf16.f32 "
        "{%0,%1,%2,%3}, {%4,%5,%6,%7}, {%8,%9}, {%0,%1,%2,%3};\n"
        : "+f"(c[0]), "+f"(c[1]), "+f"(c[2]), "+f"(c[3])
        : "r"(a[0]), "r"(a[1]), "r"(a[2]), "r"(a[3]), "r"(b0), "r"(b1));
}

// ---------------- prep: transpose + bf16-convert weights ----------------
__global__ void prep_kernel(const float* __restrict__ W1, const float* __restrict__ W2) {
    int i = blockIdx.x * blockDim.x + threadIdx.x;
    const int tot1 = HDIM * XS_STRIDE;
    if (i < tot1) {
        int n = i / XS_STRIDE, k = i - n * XS_STRIDE;
        float v = (k < FDIM + 3) ? W1[k * HDIM + n] : 0.f;
        g_w1t[i] = __float2bfloat16(v);
    } else {
        int j = i - tot1;
        if (j < KDIM * HS_STRIDE) {
            int n = j / HS_STRIDE, k = j - n * HS_STRIDE;
            float v = (k < HDIM) ? W2[k * KDIM + n] : 0.f;
            g_w2t[j] = __float2bfloat16(v);
        }
    }
}

// ---------------- fused: copy + conf + GEMM1 + GEMM2 + scatter ----------------
__global__ void __launch_bounds__(256, 1)
fused_kernel(const float* __restrict__ z, const float* __restrict__ feats,
             const float* __restrict__ b1, const float* __restrict__ b2,
             const float* __restrict__ alphas, const int* __restrict__ dom,
             float* __restrict__ out) {
    extern __shared__ __align__(16) char smem[];
    __nv_bfloat16* xs  = (__nv_bfloat16*)(smem + SM_XS);
    __nv_bfloat16* w1s = (__nv_bfloat16*)(smem + SM_W1);
    __nv_bfloat16* hs  = (__nv_bfloat16*)(smem + SM_HS);
    __nv_bfloat16* w2s = (__nv_bfloat16*)(smem + SM_W2);
    float* zs  = (float*)(smem + SM_ZS);
    float* b1s = (float*)(smem + SM_B1);
    float* b2s = (float*)(smem + SM_B2);
    int*   dms = (int*)(smem + SM_DOM);
    float* alp = (float*)(smem + SM_ALP);

    const int tid  = threadIdx.x;
    const int row0 = blockIdx.x * 128;

    // stage weights into smem (L2-hot device scratch)
    {
        const uint4* s1 = (const uint4*)g_w1t; uint4* d1 = (uint4*)w1s;
        #pragma unroll 4
        for (int i = tid; i < (HDIM * XS_STRIDE * 2) / 16; i += 256) d1[i] = s1[i];
        const uint4* s2 = (const uint4*)g_w2t; uint4* d2 = (uint4*)w2s;
        #pragma unroll 2
        for (int i = tid; i < (KDIM * HS_STRIDE * 2) / 16; i += 256) d2[i] = s2[i];
    }
    if (tid < HDIM) b1s[tid] = b1[tid];
    if (tid < KDIM) b2s[tid] = b2[tid];
    if (tid < NDOM) alp[tid] = alphas[tid];
    if (tid < 128)  dms[tid] = dom[row0 + tid];

    // feats -> xs (bf16), coalesced float4 reads (no dependence on dms)
    {
        const float4* f4 = (const float4*)feats + (size_t)row0 * (FDIM / 4);
        #pragma unroll 4
        for (int i = tid; i < 128 * (FDIM / 4); i += 256) {
            int r = i >> 6, c4 = i & 63;
            float4 v = f4[(size_t)r * (FDIM / 4) + c4];
            __nv_bfloat162 p0 = __floats2bfloat162_rn(v.x, v.y);
            __nv_bfloat162 p1 = __floats2bfloat162_rn(v.z, v.w);
            *(__nv_bfloat162*)(xs + r * XS_STRIDE + c4 * 4)     = p0;
            *(__nv_bfloat162*)(xs + r * XS_STRIDE + c4 * 4 + 2) = p1;
        }
    }
    __syncthreads();   // dms ready

    // stream z tile: non-owned float4 -> out, owned float4 -> zs smem
    {
        const float4* z4 = (const float4*)z + (size_t)row0 * (GCOLS / 4);
        float4*       o4 = (float4*)out     + (size_t)row0 * (GCOLS / 4);
        float4*       zs4 = (float4*)zs;
        #pragma unroll 8
        for (int i = tid; i < 128 * (GCOLS / 4); i += 256) {
            int r = i >> 7, q = i & 127;
            float4 v = z4[i];
            int qd = q - (dms[r] << 4);
            if ((unsigned)qd < 16u) zs4[r * (ZS_STRIDE / 4) + qd] = v;
            else                    o4[i] = v;
        }
    }
    __syncthreads();   // zs ready

    // conf stats: one thread per row, from zs (closed-form softmax stats)
    if (tid < 128) {
        const float* vr = zs + tid * ZS_STRIDE;
        float m1 = -3.4e38f, m2 = -3.4e38f;
        #pragma unroll
        for (int i = 0; i < 64; i++) {
            float x = vr[i];
            if (x > m1) { m2 = m1; m1 = x; }
            else if (x > m2) { m2 = x; }
        }
        float S = 0.f, T = 0.f;
        #pragma unroll
        for (int i = 0; i < 64; i++) {
            float e = __expf(vr[i] - m1);
            S += e;
            T += (vr[i] - m1) * e;
        }
        float pmax = 1.f / S;
        float ent  = __logf(S) - T * pmax;
        float marg = (1.f - __expf(m2 - m1)) * pmax;
        __nv_bfloat16* xr = xs + tid * XS_STRIDE;
        xr[256] = __float2bfloat16(pmax);
        xr[257] = __float2bfloat16(ent);
        xr[258] = __float2bfloat16(marg);
        #pragma unroll
        for (int k = 259; k < K1PAD; k++) xr[k] = __float2bfloat16(0.f);
    }
    __syncthreads();   // xs complete

    const int lane = tid & 31, wid = tid >> 5;
    const int g = lane >> 2, t = lane & 3;

    // ---------- GEMM1: [128 x 272] @ [272 x 128] -> h ----------
    {
        const int wm = wid & 3, wn = wid >> 2;    // 4(m) x 2(n), warp tile 32x64
        float c1[2][8][4];
        #pragma unroll
        for (int mi = 0; mi < 2; mi++)
            #pragma unroll
            for (int nf = 0; nf < 8; nf++)
                #pragma unroll
                for (int q = 0; q < 4; q++) c1[mi][nf][q] = 0.f;

        const unsigned* xs32  = (const unsigned*)xs;
        const unsigned* w1s32 = (const unsigned*)w1s;

        #pragma unroll 4
        for (int ks = 0; ks < 17; ks++) {
            const int kp = ks * 8 + t;
            unsigned a[2][4];
            #pragma unroll
            for (int mi = 0; mi < 2; mi++) {
                int r = wm * 32 + mi * 16 + g;
                a[mi][0] = xs32[r * 140 + kp];
                a[mi][1] = xs32[(r + 8) * 140 + kp];
                a[mi][2] = xs32[r * 140 + kp + 4];
                a[mi][3] = xs32[(r + 8) * 140 + kp + 4];
            }
            #pragma unroll
            for (int nf = 0; nf < 8; nf++) {
                int n = wn * 64 + nf * 8 + g;
                unsigned b0 = w1s32[n * 140 + kp];
                unsigned bb = w1s32[n * 140 + kp + 4];
                mma_bf16(c1[0][nf], a[0], b0, bb);
                mma_bf16(c1[1][nf], a[1], b0, bb);
            }
        }

        // bias + relu -> hs (bf16 pairs)
        unsigned* hs32 = (unsigned*)hs;
        #pragma unroll
        for (int mi = 0; mi < 2; mi++) {
            int r = wm * 32 + mi * 16 + g;
            #pragma unroll
            for (int nf = 0; nf < 8; nf++) {
                int ncol = wn * 64 + nf * 8 + 2 * t;
                float bb0 = b1s[ncol], bb1 = b1s[ncol + 1];
                float h0 = fmaxf(c1[mi][nf][0] + bb0, 0.f);
                float h1 = fmaxf(c1[mi][nf][1] + bb1, 0.f);
                float h2 = fmaxf(c1[mi][nf][2] + bb0, 0.f);
                float h3 = fmaxf(c1[mi][nf][3] + bb1, 0.f);
                __nv_bfloat162 p0 = __floats2bfloat162_rn(h0, h1);
                __nv_bfloat162 p1 = __floats2bfloat162_rn(h2, h3);
                hs32[r * 68 + wn * 32 + nf * 4 + t]       = *(unsigned*)&p0;
                hs32[(r + 8) * 68 + wn * 32 + nf * 4 + t] = *(unsigned*)&p1;
            }
        }
    }
    __syncthreads();

    // ---------- GEMM2: [128 x 128] @ [128 x 64] -> dz, fused add into zs ----------
    {
        const int wm = wid & 3, wn = wid >> 2;    // 4(m) x 2(n), warp tile 32x32
        float c2[2][4][4];
        #pragma unroll
        for (int mi = 0; mi < 2; mi++)
            #pragma unroll
            for (int nf = 0; nf < 4; nf++)
                #pragma unroll
                for (int q = 0; q < 4; q++) c2[mi][nf][q] = 0.f;

        const unsigned* hs32  = (const unsigned*)hs;
        const unsigned* w2s32 = (const unsigned*)w2s;

        #pragma unroll
        for (int ks = 0; ks < 8; ks++) {
            const int kp = ks * 8 + t;
            unsigned a[2][4];
            #pragma unroll
            for (int mi = 0; mi < 2; mi++) {
                int r = wm * 32 + mi * 16 + g;
                a[mi][0] = hs32[r * 68 + kp];
                a[mi][1] = hs32[(r + 8) * 68 + kp];
                a[mi][2] = hs32[r * 68 + kp + 4];
                a[mi][3] = hs32[(r + 8) * 68 + kp + 4];
            }
            #pragma unroll
            for (int nf = 0; nf < 4; nf++) {
                int n = wn * 32 + nf * 8 + g;
                unsigned b0 = w2s32[n * 68 + kp];
                unsigned bb = w2s32[n * 68 + kp + 4];
                mma_bf16(c2[0][nf], a[0], b0, bb);
                mma_bf16(c2[1][nf], a[1], b0, bb);
            }
        }

        // epilogue: zs += (c2 + b2) * alpha(domain)   (in place)
        #pragma unroll
        for (int mi = 0; mi < 2; mi++) {
            int rl = wm * 32 + mi * 16 + g;
            float al0 = alp[dms[rl]];
            float al1 = alp[dms[rl + 8]];
            #pragma unroll
            for (int nf = 0; nf < 4; nf++) {
                int col = wn * 32 + nf * 8 + 2 * t;
                float bb0 = b2s[col], bb1 = b2s[col + 1];
                float2* p0 = (float2*)&zs[rl * ZS_STRIDE + col];
                float2* p1 = (float2*)&zs[(rl + 8) * ZS_STRIDE + col];
                float2 v0 = *p0, v1 = *p1;
                v0.x += (c2[mi][nf][0] + bb0) * al0;
                v0.y += (c2[mi][nf][1] + bb1) * al0;
                v1.x += (c2[mi][nf][2] + bb0) * al1;
                v1.y += (c2[mi][nf][3] + bb1) * al1;
                *p0 = v0; *p1 = v1;
            }
        }
    }
    __syncthreads();

    // write owned slices back (256B contiguous per row)
    {
        const float4* zs4 = (const float4*)zs;
        float4* o4 = (float4*)out + (size_t)row0 * (GCOLS / 4);
        #pragma unroll 8
        for (int i = tid; i < 128 * 16; i += 256) {
            int r = i >> 4, qd = i & 15;
            o4[r * 128 + (dms[r] << 4) + qd] = zs4[r * (ZS_STRIDE / 4) + qd];
        }
    }
}

extern "C" void kernel_launch(void* const* d_in, const int* in_sizes, int n_in,
                              void* d_out, int out_size) {
    const float* z      = (const float*)d_in[0];
    const float* feats  = (const float*)d_in[1];
    const float* W1     = (const float*)d_in[2];
    const float* b1     = (const float*)d_in[3];
    const float* W2     = (const float*)d_in[4];
    const float* b2     = (const float*)d_in[5];
    const float* alphas = (const float*)d_in[6];
    const int*   dom    = (const int*)d_in[7];
    float* out = (float*)d_out;

    cudaFuncSetAttribute(fused_kernel, cudaFuncAttributeMaxDynamicSharedMemorySize,
                         SMEM_BYTES);

    const int preptot = HDIM * XS_STRIDE + KDIM * HS_STRIDE;
    prep_kernel<<<(preptot + 255) / 256, 256>>>(W1, W2);
    fused_kernel<<<NROWS / 128, 256, SMEM_BYTES>>>(z, feats, b1, b2, alphas, dom, out);
}

// round 9
// speedup vs baseline: 1.1855x; 1.1621x over previous
#include <cuda_runtime.h>
#include <cuda_bf16.h>

#define NROWS 131072
#define GCOLS 512
#define FDIM  256
#define HDIM  128
#define KDIM  64
#define NDOM  8

#define K1PAD 272          // GEMM1 K padded: 259 -> 272 (17 k16 steps)
#define XS_STRIDE 280      // bf16 stride for x / W1^T (140 b32, conflict-free frag loads)
#define HS_STRIDE 136      // bf16 stride for h / W2^T (68 b32)
#define ZS_STRIDE 68       // f32 stride for owned z slice (17 float4 per row)

#define NTHREADS 384       // 8 compute warps + 4 copy warps

// ---------------- device scratch (no allocations allowed) ----------------
__device__ __align__(16) __nv_bfloat16 g_w1t[HDIM * XS_STRIDE];   // [n][k] = W1[k][n]
__device__ __align__(16) __nv_bfloat16 g_w2t[KDIM * HS_STRIDE];   // [n][k] = W2[k][n]

// ---------------- smem layout (bytes) ----------------
#define SM_XS   0                          // 128*280*2 = 71680
#define SM_W1   71680                      // 71680
#define SM_HS   143360                     // 128*136*2 = 34816
#define SM_W2   178176                     // 64*136*2  = 17408
#define SM_ZS   195584                     // 128*68*4  = 34816
#define SM_B1   230400                     // 512
#define SM_B2   230912                     // 256
#define SM_DOM  231168                     // 512
#define SM_ALP  231680                     // 32
#define SMEM_BYTES 231712

// named barriers
#define BAR_SYNC(id, cnt)   asm volatile("bar.sync %0, %1;"   :: "n"(id), "n"(cnt) : "memory")
#define BAR_ARRIVE(id, cnt) asm volatile("bar.arrive %0, %1;" :: "n"(id), "n"(cnt) : "memory")
// id 2: zs ready       (copy arrives 128, compute syncs 256; total 384)
// id 3: dz done        (compute arrives 256, copy syncs 128; total 384)
// id 4: compute-internal (256), reused sequentially

// m16n8k16 row.col bf16 -> f32 accumulate
__device__ __forceinline__ void mma_bf16(float (&c)[4], const unsigned (&a)[4],
                                         unsigned b0, unsigned b1) {
    asm volatile(
        "mma.sync.aligned.m16n8k16.row.col.f32.bf16.bf16.f32 "
        "{%0,%1,%2,%3}, {%4,%5,%6,%7}, {%8,%9}, {%0,%1,%2,%3};\n"
        : "+f"(c[0]), "+f"(c[1]), "+f"(c[2]), "+f"(c[3])
        : "r"(a[0]), "r"(a[1]), "r"(a[2]), "r"(a[3]), "r"(b0), "r"(b1));
}

// ---------------- prep: transpose + bf16-convert weights ----------------
__global__ void prep_kernel(const float* __restrict__ W1, const float* __restrict__ W2) {
    int i = blockIdx.x * blockDim.x + threadIdx.x;
    const int tot1 = HDIM * XS_STRIDE;
    if (i < tot1) {
        int n = i / XS_STRIDE, k = i - n * XS_STRIDE;
        float v = (k < FDIM + 3) ? W1[k * HDIM + n] : 0.f;
        g_w1t[i] = __float2bfloat16(v);
    } else {
        int j = i - tot1;
        if (j < KDIM * HS_STRIDE) {
            int n = j / HS_STRIDE, k = j - n * HS_STRIDE;
            float v = (k < HDIM) ? W2[k * KDIM + n] : 0.f;
            g_w2t[j] = __float2bfloat16(v);
        }
    }
}

// ---------------- fused, warp-specialized ----------------
__global__ void __launch_bounds__(NTHREADS, 1)
fused_kernel(const float* __restrict__ z, const float* __restrict__ feats,
             const float* __restrict__ b1, const float* __restrict__ b2,
             const float* __restrict__ alphas, const int* __restrict__ dom,
             float* __restrict__ out) {
    extern __shared__ __align__(16) char smem[];
    __nv_bfloat16* xs  = (__nv_bfloat16*)(smem + SM_XS);
    __nv_bfloat16* w1s = (__nv_bfloat16*)(smem + SM_W1);
    __nv_bfloat16* hs  = (__nv_bfloat16*)(smem + SM_HS);
    __nv_bfloat16* w2s = (__nv_bfloat16*)(smem + SM_W2);
    float* zs  = (float*)(smem + SM_ZS);
    float* b1s = (float*)(smem + SM_B1);
    float* b2s = (float*)(smem + SM_B2);
    int*   dms = (int*)(smem + SM_DOM);
    float* alp = (float*)(smem + SM_ALP);

    const int tid  = threadIdx.x;
    const int row0 = blockIdx.x * 128;

    // ---- common prologue: weights, biases, domains (all 384 threads) ----
    {
        const uint4* s1 = (const uint4*)g_w1t; uint4* d1 = (uint4*)w1s;
        #pragma unroll 4
        for (int i = tid; i < (HDIM * XS_STRIDE * 2) / 16; i += NTHREADS) d1[i] = s1[i];
        const uint4* s2 = (const uint4*)g_w2t; uint4* d2 = (uint4*)w2s;
        #pragma unroll 2
        for (int i = tid; i < (KDIM * HS_STRIDE * 2) / 16; i += NTHREADS) d2[i] = s2[i];
    }
    if (tid < HDIM) b1s[tid] = b1[tid];
    if (tid < KDIM) b2s[tid] = b2[tid];
    if (tid < NDOM) alp[tid] = alphas[tid];
    if (tid < 128)  dms[tid] = dom[row0 + tid];
    __syncthreads();   // dms + weights + biases ready

    if (tid >= 256) {
        // ================= COPY WARPS (128 threads) =================
        const int ctid = tid - 256;
        const float4* z4  = (const float4*)z + (size_t)row0 * (GCOLS / 4);
        float4*       o4  = (float4*)out     + (size_t)row0 * (GCOLS / 4);
        float4*       zs4 = (float4*)zs;

        // 1) owned slice -> zs   (8 rows x 16 f4 per sweep, coalesced 256B/row)
        #pragma unroll
        for (int i = ctid; i < 128 * 16; i += 128) {
            int r = i >> 4, qd = i & 15;
            zs4[r * (ZS_STRIDE / 4) + qd] = z4[r * 128 + (dms[r] << 4) + qd];
        }
        BAR_ARRIVE(2, NTHREADS);           // zs ready

        // 2) bulk passthrough: entire z tile -> out (owned region overwritten later)
        #pragma unroll 16
        for (int i = ctid; i < 128 * (GCOLS / 4); i += 128) {
            o4[i] = z4[i];
        }

        // 3) wait for dz, write final owned slices
        BAR_SYNC(3, NTHREADS);             // dz done (epilogue added into zs)
        #pragma unroll
        for (int i = ctid; i < 128 * 16; i += 128) {
            int r = i >> 4, qd = i & 15;
            o4[r * 128 + (dms[r] << 4) + qd] = zs4[r * (ZS_STRIDE / 4) + qd];
        }
        return;
    }

    // ================= COMPUTE WARPS (256 threads) =================
    // feats -> xs (bf16), coalesced float4 reads
    {
        const float4* f4 = (const float4*)feats + (size_t)row0 * (FDIM / 4);
        #pragma unroll 8
        for (int i = tid; i < 128 * (FDIM / 4); i += 256) {
            int r = i >> 6, c4 = i & 63;
            float4 v = f4[(size_t)r * (FDIM / 4) + c4];
            __nv_bfloat162 p0 = __floats2bfloat162_rn(v.x, v.y);
            __nv_bfloat162 p1 = __floats2bfloat162_rn(v.z, v.w);
            *(__nv_bfloat162*)(xs + r * XS_STRIDE + c4 * 4)     = p0;
            *(__nv_bfloat162*)(xs + r * XS_STRIDE + c4 * 4 + 2) = p1;
        }
    }

    BAR_SYNC(2, NTHREADS);   // zs ready (from copy warps)

    // conf stats: one thread per row (closed-form softmax stats)
    if (tid < 128) {
        const float* vr = zs + tid * ZS_STRIDE;
        float m1 = -3.4e38f, m2 = -3.4e38f;
        #pragma unroll
        for (int i = 0; i < 64; i++) {
            float x = vr[i];
            if (x > m1) { m2 = m1; m1 = x; }
            else if (x > m2) { m2 = x; }
        }
        float S = 0.f, T = 0.f;
        #pragma unroll
        for (int i = 0; i < 64; i++) {
            float e = __expf(vr[i] - m1);
            S += e;
            T += (vr[i] - m1) * e;
        }
        float pmax = 1.f / S;
        float ent  = __logf(S) - T * pmax;
        float marg = (1.f - __expf(m2 - m1)) * pmax;
        __nv_bfloat16* xr = xs + tid * XS_STRIDE;
        xr[256] = __float2bfloat16(pmax);
        xr[257] = __float2bfloat16(ent);
        xr[258] = __float2bfloat16(marg);
        #pragma unroll
        for (int k = 259; k < K1PAD; k++) xr[k] = __float2bfloat16(0.f);
    }
    BAR_SYNC(4, 256);        // xs complete (feats + conf)

    const int lane = tid & 31, wid = tid >> 5;
    const int g = lane >> 2, t = lane & 3;

    // ---------- GEMM1: [128 x 272] @ [272 x 128] -> h ----------
    {
        const int wm = wid & 3, wn = wid >> 2;    // 4(m) x 2(n), warp tile 32x64
        float c1[2][8][4];
        #pragma unroll
        for (int mi = 0; mi < 2; mi++)
            #pragma unroll
            for (int nf = 0; nf < 8; nf++)
                #pragma unroll
                for (int q = 0; q < 4; q++) c1[mi][nf][q] = 0.f;

        const unsigned* xs32  = (const unsigned*)xs;
        const unsigned* w1s32 = (const unsigned*)w1s;

        #pragma unroll 4
        for (int ks = 0; ks < 17; ks++) {
            const int kp = ks * 8 + t;
            unsigned a[2][4];
            #pragma unroll
            for (int mi = 0; mi < 2; mi++) {
                int r = wm * 32 + mi * 16 + g;
                a[mi][0] = xs32[r * 140 + kp];
                a[mi][1] = xs32[(r + 8) * 140 + kp];
                a[mi][2] = xs32[r * 140 + kp + 4];
                a[mi][3] = xs32[(r + 8) * 140 + kp + 4];
            }
            #pragma unroll
            for (int nf = 0; nf < 8; nf++) {
                int n = wn * 64 + nf * 8 + g;
                unsigned b0 = w1s32[n * 140 + kp];
                unsigned bb = w1s32[n * 140 + kp + 4];
                mma_bf16(c1[0][nf], a[0], b0, bb);
                mma_bf16(c1[1][nf], a[1], b0, bb);
            }
        }

        // bias + relu -> hs (bf16 pairs)
        unsigned* hs32 = (unsigned*)hs;
        #pragma unroll
        for (int mi = 0; mi < 2; mi++) {
            int r = wm * 32 + mi * 16 + g;
            #pragma unroll
            for (int nf = 0; nf < 8; nf++) {
                int ncol = wn * 64 + nf * 8 + 2 * t;
                float bb0 = b1s[ncol], bb1 = b1s[ncol + 1];
                float h0 = fmaxf(c1[mi][nf][0] + bb0, 0.f);
                float h1 = fmaxf(c1[mi][nf][1] + bb1, 0.f);
                float h2 = fmaxf(c1[mi][nf][2] + bb0, 0.f);
                float h3 = fmaxf(c1[mi][nf][3] + bb1, 0.f);
                __nv_bfloat162 p0 = __floats2bfloat162_rn(h0, h1);
                __nv_bfloat162 p1 = __floats2bfloat162_rn(h2, h3);
                hs32[r * 68 + wn * 32 + nf * 4 + t]       = *(unsigned*)&p0;
                hs32[(r + 8) * 68 + wn * 32 + nf * 4 + t] = *(unsigned*)&p1;
            }
        }
    }
    BAR_SYNC(4, 256);        // hs ready

    // ---------- GEMM2: [128 x 128] @ [128 x 64] -> dz, fused add into zs ----------
    {
        const int wm = wid & 3, wn = wid >> 2;    // 4(m) x 2(n), warp tile 32x32
        float c2[2][4][4];
        #pragma unroll
        for (int mi = 0; mi < 2; mi++)
            #pragma unroll
            for (int nf = 0; nf < 4; nf++)
                #pragma unroll
                for (int q = 0; q < 4; q++) c2[mi][nf][q] = 0.f;

        const unsigned* hs32  = (const unsigned*)hs;
        const unsigned* w2s32 = (const unsigned*)w2s;

        #pragma unroll
        for (int ks = 0; ks < 8; ks++) {
            const int kp = ks * 8 + t;
            unsigned a[2][4];
            #pragma unroll
            for (int mi = 0; mi < 2; mi++) {
                int r = wm * 32 + mi * 16 + g;
                a[mi][0] = hs32[r * 68 + kp];
                a[mi][1] = hs32[(r + 8) * 68 + kp];
                a[mi][2] = hs32[r * 68 + kp + 4];
                a[mi][3] = hs32[(r + 8) * 68 + kp + 4];
            }
            #pragma unroll
            for (int nf = 0; nf < 4; nf++) {
                int n = wn * 32 + nf * 8 + g;
                unsigned b0 = w2s32[n * 68 + kp];
                unsigned bb = w2s32[n * 68 + kp + 4];
                mma_bf16(c2[0][nf], a[0], b0, bb);
                mma_bf16(c2[1][nf], a[1], b0, bb);
            }
        }

        // epilogue: zs += (c2 + b2) * alpha(domain)   (in place)
        #pragma unroll
        for (int mi = 0; mi < 2; mi++) {
            int rl = wm * 32 + mi * 16 + g;
            float al0 = alp[dms[rl]];
            float al1 = alp[dms[rl + 8]];
            #pragma unroll
            for (int nf = 0; nf < 4; nf++) {
                int col = wn * 32 + nf * 8 + 2 * t;
                float bb0 = b2s[col], bb1 = b2s[col + 1];
                float2* p0 = (float2*)&zs[rl * ZS_STRIDE + col];
                float2* p1 = (float2*)&zs[(rl + 8) * ZS_STRIDE + col];
                float2 v0 = *p0, v1 = *p1;
                v0.x += (c2[mi][nf][0] + bb0) * al0;
                v0.y += (c2[mi][nf][1] + bb1) * al0;
                v1.x += (c2[mi][nf][2] + bb0) * al1;
                v1.y += (c2[mi][nf][3] + bb1) * al1;
                *p0 = v0; *p1 = v1;
            }
        }
    }
    BAR_ARRIVE(3, NTHREADS);   // dz done -> copy warps write the owned slices
}

extern "C" void kernel_launch(void* const* d_in, const int* in_sizes, int n_in,
                              void* d_out, int out_size) {
    const float* z      = (const float*)d_in[0];
    const float* feats  = (const float*)d_in[1];
    const float* W1     = (const float*)d_in[2];
    const float* b1     = (const float*)d_in[3];
    const float* W2     = (const float*)d_in[4];
    const float* b2     = (const float*)d_in[5];
    const float* alphas = (const float*)d_in[6];
    const int*   dom    = (const int*)d_in[7];
    float* out = (float*)d_out;

    cudaFuncSetAttribute(fused_kernel, cudaFuncAttributeMaxDynamicSharedMemorySize,
                         SMEM_BYTES);

    const int preptot = HDIM * XS_STRIDE + KDIM * HS_STRIDE;
    prep_kernel<<<(preptot + 255) / 256, 256>>>(W1, W2);
    fused_kernel<<<NROWS / 128, NTHREADS, SMEM_BYTES>>>(z, feats, b1, b2, alphas, dom, out);
}

// round 10
// speedup vs baseline: 1.2857x; 1.0845x over previous
#include <cuda_runtime.h>
#include <cuda_bf16.h>

#define NROWS 131072
#define GCOLS 512
#define FDIM  256
#define HDIM  128
#define KDIM  64
#define NDOM  8
#define NTILES (NROWS / 128)

#define K1PAD 272          // GEMM1 K padded: 259 -> 272 (17 k16 steps)
#define XS_STRIDE 280      // bf16 stride for x / W1^T (140 b32, conflict-free frag loads)
#define HS_STRIDE 136      // bf16 stride for h / W2^T (68 b32)
#define ZS_STRIDE 68       // f32 stride for owned z slice (17 float4 per row)

#define NTHREADS 384       // 8 compute warps + 4 copy warps
#define COPY_ROWS 96       // rows [0,96) bulk-copied by copy engine; [96,128) by compute

// ---------------- device scratch (no allocations allowed) ----------------
__device__ __align__(16) __nv_bfloat16 g_w1t[HDIM * XS_STRIDE];   // [n][k] = W1[k][n]
__device__ __align__(16) __nv_bfloat16 g_w2t[KDIM * HS_STRIDE];   // [n][k] = W2[k][n]

// ---------------- smem layout (bytes) ----------------
#define SM_XS   0                          // 128*280*2 = 71680
#define SM_W1   71680                      // 71680
#define SM_HS   143360                     // 128*136*2 = 34816
#define SM_W2   178176                     // 64*136*2  = 17408
#define SM_ZS   195584                     // 128*68*4  = 34816
#define SM_B1   230400                     // 512
#define SM_B2   230912                     // 256
#define SM_DOM  231168                     // 512
#define SM_ALP  231680                     // 32
#define SMEM_BYTES 231712

#define BAR_SYNC4() asm volatile("bar.sync 4, 256;" ::: "memory")

// m16n8k16 row.col bf16 -> f32 accumulate
__device__ __forceinline__ void mma_bf16(float (&c)[4], const unsigned (&a)[4],
                                         unsigned b0, unsigned b1) {
    asm volatile(
        "mma.sync.aligned.m16n8k16.row.col.f32.bf16.bf16.f32 "
        "{%0,%1,%2,%3}, {%4,%5,%6,%7}, {%8,%9}, {%0,%1,%2,%3};\n"
        : "+f"(c[0]), "+f"(c[1]), "+f"(c[2]), "+f"(c[3])
        : "r"(a[0]), "r"(a[1]), "r"(a[2]), "r"(a[3]), "r"(b0), "r"(b1));
}

// ---------------- prep: transpose + bf16-convert weights ----------------
__global__ void prep_kernel(const float* __restrict__ W1, const float* __restrict__ W2) {
    int i = blockIdx.x * blockDim.x + threadIdx.x;
    const int tot1 = HDIM * XS_STRIDE;
    if (i < tot1) {
        int n = i / XS_STRIDE, k = i - n * XS_STRIDE;
        float v = (k < FDIM + 3) ? W1[k * HDIM + n] : 0.f;
        g_w1t[i] = __float2bfloat16(v);
    } else {
        int j = i - tot1;
        if (j < KDIM * HS_STRIDE) {
            int n = j / HS_STRIDE, k = j - n * HS_STRIDE;
            float v = (k < HDIM) ? W2[k * KDIM + n] : 0.f;
            g_w2t[j] = __float2bfloat16(v);
        }
    }
}

// ---------------- persistent fused kernel, decoupled engines ----------------
__global__ void __launch_bounds__(NTHREADS, 1)
fused_kernel(const float* __restrict__ z, const float* __restrict__ feats,
             const float* __restrict__ b1, const float* __restrict__ b2,
             const float* __restrict__ alphas, const int* __restrict__ dom,
             float* __restrict__ out) {
    extern __shared__ __align__(16) char smem[];
    __nv_bfloat16* xs  = (__nv_bfloat16*)(smem + SM_XS);
    __nv_bfloat16* w1s = (__nv_bfloat16*)(smem + SM_W1);
    __nv_bfloat16* hs  = (__nv_bfloat16*)(smem + SM_HS);
    __nv_bfloat16* w2s = (__nv_bfloat16*)(smem + SM_W2);
    float* zs  = (float*)(smem + SM_ZS);
    float* b1s = (float*)(smem + SM_B1);
    float* b2s = (float*)(smem + SM_B2);
    int*   dms = (int*)(smem + SM_DOM);
    float* alp = (float*)(smem + SM_ALP);

    const int tid = threadIdx.x;

    // ---- one-time prologue (all 384 threads) ----
    {
        const uint4* s1 = (const uint4*)g_w1t; uint4* d1 = (uint4*)w1s;
        #pragma unroll 4
        for (int i = tid; i < (HDIM * XS_STRIDE * 2) / 16; i += NTHREADS) d1[i] = s1[i];
        const uint4* s2 = (const uint4*)g_w2t; uint4* d2 = (uint4*)w2s;
        #pragma unroll 2
        for (int i = tid; i < (KDIM * HS_STRIDE * 2) / 16; i += NTHREADS) d2[i] = s2[i];
    }
    if (tid < HDIM) b1s[tid] = b1[tid];
    if (tid < KDIM) b2s[tid] = b2[tid];
    if (tid < NDOM) alp[tid] = alphas[tid];
    __syncthreads();   // weights/biases ready; engines decouple after this

    if (tid >= 256) {
        // ================= COPY ENGINE (4 warps, barrier-free) =================
        // writes the NON-OWNED columns of rows [0, COPY_ROWS) of each tile
        const int ctid = tid - 256;        // 0..127 == column f4 index
        const int cb   = ctid >> 4;        // which 16-f4 block this column lies in
        for (int tile = blockIdx.x; tile < NTILES; tile += gridDim.x) {
            const int row0 = tile * 128;
            const float4* z4 = (const float4*)z + (size_t)row0 * (GCOLS / 4);
            float4*       o4 = (float4*)out     + (size_t)row0 * (GCOLS / 4);
            const int* dr = dom + row0;
            #pragma unroll 8
            for (int r = 0; r < COPY_ROWS; r++) {
                int d = __ldg(dr + r);
                if (cb != d) o4[r * 128 + ctid] = z4[r * 128 + ctid];
            }
        }
        return;
    }

    // ================= COMPUTE ENGINE (8 warps) =================
    const int lane = tid & 31, wid = tid >> 5;
    const int g = lane >> 2, t = lane & 3;

    for (int tile = blockIdx.x; tile < NTILES; tile += gridDim.x) {
        const int row0 = tile * 128;
        const float4* z4 = (const float4*)z + (size_t)row0 * (GCOLS / 4);
        float4*       o4 = (float4*)out     + (size_t)row0 * (GCOLS / 4);
        float4*       zs4 = (float4*)zs;
        const int* dr = dom + row0;

        BAR_SYNC4();   // zs/dms from previous tile fully consumed

        // --- memory phase: feats -> xs, owned slice -> zs, rows [96,128) passthrough ---
        {
            const float4* f4 = (const float4*)feats + (size_t)row0 * (FDIM / 4);
            #pragma unroll 8
            for (int i = tid; i < 128 * (FDIM / 4); i += 256) {
                int r = i >> 6, c4 = i & 63;
                float4 v = f4[(size_t)r * (FDIM / 4) + c4];
                __nv_bfloat162 p0 = __floats2bfloat162_rn(v.x, v.y);
                __nv_bfloat162 p1 = __floats2bfloat162_rn(v.z, v.w);
                *(__nv_bfloat162*)(xs + r * XS_STRIDE + c4 * 4)     = p0;
                *(__nv_bfloat162*)(xs + r * XS_STRIDE + c4 * 4 + 2) = p1;
            }
            // owned slice -> zs (coalesced: warp covers 2 rows x 256B)
            #pragma unroll 8
            for (int i = tid; i < 128 * 16; i += 256) {
                int r = i >> 4, qd = i & 15;
                int d = __ldg(dr + r);
                zs4[r * (ZS_STRIDE / 4) + qd] = z4[r * 128 + (d << 4) + qd];
            }
            // rows [96,128): non-owned passthrough z -> out
            #pragma unroll 8
            for (int i = tid; i < (128 - COPY_ROWS) * 128; i += 256) {
                int r = COPY_ROWS + (i >> 7), q = i & 127;
                int d = __ldg(dr + r);
                if ((q >> 4) != d) o4[r * 128 + q] = z4[r * 128 + q];
            }
        }
        BAR_SYNC4();   // zs ready

        // --- conf stats: one thread per row, from zs ---
        if (tid < 128) {
            dms[tid] = __ldg(dr + tid);
            const float4* vr4 = (const float4*)(zs + tid * ZS_STRIDE);
            float v[64];
            #pragma unroll
            for (int i = 0; i < 16; i++) {
                float4 tv = vr4[i];
                v[4*i] = tv.x; v[4*i+1] = tv.y; v[4*i+2] = tv.z; v[4*i+3] = tv.w;
            }
            float m1 = -3.4e38f, m2 = -3.4e38f;
            #pragma unroll
            for (int i = 0; i < 64; i++) {
                float x = v[i];
                if (x > m1) { m2 = m1; m1 = x; }
                else if (x > m2) { m2 = x; }
            }
            float S = 0.f, T = 0.f;
            #pragma unroll
            for (int i = 0; i < 64; i++) {
                float e = __expf(v[i] - m1);
                S += e;
                T += (v[i] - m1) * e;
            }
            float pmax = 1.f / S;
            float ent  = __logf(S) - T * pmax;
            float marg = (1.f - __expf(m2 - m1)) * pmax;
            __nv_bfloat16* xr = xs + tid * XS_STRIDE;
            xr[256] = __float2bfloat16(pmax);
            xr[257] = __float2bfloat16(ent);
            xr[258] = __float2bfloat16(marg);
            #pragma unroll
            for (int k = 259; k < K1PAD; k++) xr[k] = __float2bfloat16(0.f);
        }
        BAR_SYNC4();   // xs complete, dms ready

        // ---------- GEMM1: [128 x 272] @ [272 x 128] -> h ----------
        {
            const int wm = wid & 3, wn = wid >> 2;    // 4(m) x 2(n), warp tile 32x64
            float c1[2][8][4];
            #pragma unroll
            for (int mi = 0; mi < 2; mi++)
                #pragma unroll
                for (int nf = 0; nf < 8; nf++)
                    #pragma unroll
                    for (int q = 0; q < 4; q++) c1[mi][nf][q] = 0.f;

            const unsigned* xs32  = (const unsigned*)xs;
            const unsigned* w1s32 = (const unsigned*)w1s;

            #pragma unroll 4
            for (int ks = 0; ks < 17; ks++) {
                const int kp = ks * 8 + t;
                unsigned a[2][4];
                #pragma unroll
                for (int mi = 0; mi < 2; mi++) {
                    int r = wm * 32 + mi * 16 + g;
                    a[mi][0] = xs32[r * 140 + kp];
                    a[mi][1] = xs32[(r + 8) * 140 + kp];
                    a[mi][2] = xs32[r * 140 + kp + 4];
                    a[mi][3] = xs32[(r + 8) * 140 + kp + 4];
                }
                #pragma unroll
                for (int nf = 0; nf < 8; nf++) {
                    int n = wn * 64 + nf * 8 + g;
                    unsigned b0 = w1s32[n * 140 + kp];
                    unsigned bb = w1s32[n * 140 + kp + 4];
                    mma_bf16(c1[0][nf], a[0], b0, bb);
                    mma_bf16(c1[1][nf], a[1], b0, bb);
                }
            }

            // bias + relu -> hs (bf16 pairs)
            unsigned* hs32 = (unsigned*)hs;
            #pragma unroll
            for (int mi = 0; mi < 2; mi++) {
                int r = wm * 32 + mi * 16 + g;
                #pragma unroll
                for (int nf = 0; nf < 8; nf++) {
                    int ncol = wn * 64 + nf * 8 + 2 * t;
                    float bb0 = b1s[ncol], bb1 = b1s[ncol + 1];
                    float h0 = fmaxf(c1[mi][nf][0] + bb0, 0.f);
                    float h1 = fmaxf(c1[mi][nf][1] + bb1, 0.f);
                    float h2 = fmaxf(c1[mi][nf][2] + bb0, 0.f);
                    float h3 = fmaxf(c1[mi][nf][3] + bb1, 0.f);
                    __nv_bfloat162 p0 = __floats2bfloat162_rn(h0, h1);
                    __nv_bfloat162 p1 = __floats2bfloat162_rn(h2, h3);
                    hs32[r * 68 + wn * 32 + nf * 4 + t]       = *(unsigned*)&p0;
                    hs32[(r + 8) * 68 + wn * 32 + nf * 4 + t] = *(unsigned*)&p1;
                }
            }
        }
        BAR_SYNC4();   // hs ready

        // ---------- GEMM2: [128 x 128] @ [128 x 64] -> dz, add into zs ----------
        {
            const int wm = wid & 3, wn = wid >> 2;    // warp tile 32x32
            float c2[2][4][4];
            #pragma unroll
            for (int mi = 0; mi < 2; mi++)
                #pragma unroll
                for (int nf = 0; nf < 4; nf++)
                    #pragma unroll
                    for (int q = 0; q < 4; q++) c2[mi][nf][q] = 0.f;

            const unsigned* hs32  = (const unsigned*)hs;
            const unsigned* w2s32 = (const unsigned*)w2s;

            #pragma unroll
            for (int ks = 0; ks < 8; ks++) {
                const int kp = ks * 8 + t;
                unsigned a[2][4];
                #pragma unroll
                for (int mi = 0; mi < 2; mi++) {
                    int r = wm * 32 + mi * 16 + g;
                    a[mi][0] = hs32[r * 68 + kp];
                    a[mi][1] = hs32[(r + 8) * 68 + kp];
                    a[mi][2] = hs32[r * 68 + kp + 4];
                    a[mi][3] = hs32[(r + 8) * 68 + kp + 4];
                }
                #pragma unroll
                for (int nf = 0; nf < 4; nf++) {
                    int n = wn * 32 + nf * 8 + g;
                    unsigned b0 = w2s32[n * 68 + kp];
                    unsigned bb = w2s32[n * 68 + kp + 4];
                    mma_bf16(c2[0][nf], a[0], b0, bb);
                    mma_bf16(c2[1][nf], a[1], b0, bb);
                }
            }

            // epilogue: zs += (c2 + b2) * alpha(domain)
            #pragma unroll
            for (int mi = 0; mi < 2; mi++) {
                int rl = wm * 32 + mi * 16 + g;
                float al0 = alp[dms[rl]];
                float al1 = alp[dms[rl + 8]];
                #pragma unroll
                for (int nf = 0; nf < 4; nf++) {
                    int col = wn * 32 + nf * 8 + 2 * t;
                    float bb0 = b2s[col], bb1 = b2s[col + 1];
                    float2* p0 = (float2*)&zs[rl * ZS_STRIDE + col];
                    float2* p1 = (float2*)&zs[(rl + 8) * ZS_STRIDE + col];
                    float2 v0 = *p0, v1 = *p1;
                    v0.x += (c2[mi][nf][0] + bb0) * al0;
                    v0.y += (c2[mi][nf][1] + bb1) * al0;
                    v1.x += (c2[mi][nf][2] + bb0) * al1;
                    v1.y += (c2[mi][nf][3] + bb1) * al1;
                    *p0 = v0; *p1 = v1;
                }
            }
        }
        BAR_SYNC4();   // zs final

        // --- owned-slice writeback for ALL 128 rows (256B contiguous per row) ---
        #pragma unroll 4
        for (int i = tid; i < 128 * 16; i += 256) {
            int r = i >> 4, qd = i & 15;
            o4[r * 128 + (dms[r] << 4) + qd] = zs4[r * (ZS_STRIDE / 4) + qd];
        }
    }
}

extern "C" void kernel_launch(void* const* d_in, const int* in_sizes, int n_in,
                              void* d_out, int out_size) {
    const float* z      = (const float*)d_in[0];
    const float* feats  = (const float*)d_in[1];
    const float* W1     = (const float*)d_in[2];
    const float* b1     = (const float*)d_in[3];
    const float* W2     = (const float*)d_in[4];
    const float* b2     = (const float*)d_in[5];
    const float* alphas = (const float*)d_in[6];
    const int*   dom    = (const int*)d_in[7];
    float* out = (float*)d_out;

    cudaFuncSetAttribute(fused_kernel, cudaFuncAttributeMaxDynamicSharedMemorySize,
                         SMEM_BYTES);

    int dev = 0, nsm = 148;
    cudaGetDevice(&dev);
    cudaDeviceGetAttribute(&nsm, cudaDevAttrMultiProcessorCount, dev);
    if (nsm <= 0 || nsm > NTILES) nsm = 148;

    const int preptot = HDIM * XS_STRIDE + KDIM * HS_STRIDE;
    prep_kernel<<<(preptot + 255) / 256, 256>>>(W1, W2);
    fused_kernel<<<nsm, NTHREADS, SMEM_BYTES>>>(z, feats, b1, b2, alphas, dom, out);
}